// round 15
// baseline (speedup 1.0000x reference)
#include <cuda_runtime.h>
#include <cmath>
#include <complex>
#include <algorithm>

// ----------------------------------------------------------------------------
// Problem constants
// ----------------------------------------------------------------------------
#define NNODES   50000
#define C_DIM    128
#define M_DIM    9
#define B_NODES  16
#define THREADS  512

// x region (b32 = bf16x2 words)
#define XSTRIDE  68                        // row stride words (==4 mod 32), 272 B
#define SXW      (144 * XSTRIDE)           // 9792 words per x part (hi / lo)
#define OFF_XH   0
#define OFF_XL   (SXW)

// weight chunk buffers: stride 36 words (144 B, ==4 mod 32, 16B-aligned rows)
#define WSTRIDE  36
#define PART_W   (128 * WSTRIDE)           // 4608 words per part
#define WBUF_WORDS (4 * PART_W)            // 18432 words (A chunks use 4 parts)
#define WBUF0    (2 * SXW)                 // 19584
#define SMEM_WORDS (2 * SXW + 2 * WBUF_WORDS)  // 56448 words
#define SMEM_BYTES (SMEM_WORDS * 4)            // 225792 B

// Pre-split weight scratch, chunk-major:
//  A chunks 0..5  = (l, khalf): 16384 words = [part: WLh,WLl,WRh,WRl][row 128][32]
//  C chunks 6..11 = (l, khalf):  8192 words = [part: WFh,WFl][row 128][32]
#define GWC_A    16384
#define GWC_C    8192
#define GW_C0    (6 * GWC_A)               // 98304
#define GW_WORDS 147456
__device__ __align__(16) unsigned g_wsplit[GW_WORDS];

// Wigner-3j tables (alpha folded in), kernel arg.
struct W3J {
    float w220[25];
    float w121[45];
    float w112[45];
};

// ----------------------------------------------------------------------------
// Host-side Wigner 3j (literal translation of the reference, double precision)
// ----------------------------------------------------------------------------
namespace hw3j {
typedef std::complex<double> cd;

static inline double fact(int n) { double r = 1.0; for (int i = 2; i <= n; ++i) r *= (double)i; return r; }

static double su2_cg(int j1, int m1, int j2, int m2, int j3, int m3) {
    if (m1 + m2 != m3) return 0.0;
    int vmin = std::max(std::max(-j1 + j2 + m3, -j1 + m1), 0);
    int vmax = std::min(std::min(j2 + j3 + m1, j3 - j1 + j2), j3 + m3);
    double pref = std::sqrt((2.0 * j3 + 1.0)
        * fact(j3 + j1 - j2) * fact(j3 - j1 + j2) * fact(j1 + j2 - j3) / fact(j1 + j2 + j3 + 1)
        * fact(j3 + m3) * fact(j3 - m3)
        / (fact(j1 - m1) * fact(j1 + m1) * fact(j2 - m2) * fact(j2 + m2)));
    double s = 0.0;
    for (int v = vmin; v <= vmax; ++v) {
        double sgn = ((v + j2 + m2) & 1) ? -1.0 : 1.0;
        s += sgn / fact(v) * fact(j2 + j3 + m1 - v) * fact(j1 - m1 + v)
             / (fact(j3 - j1 + j2 - v) * fact(j3 + m3 - v) * fact(v + j1 - j2 - m3));
    }
    return pref * s;
}

static void qmat(int l, cd q[5][5]) {
    for (int a = 0; a < 5; ++a) for (int b = 0; b < 5; ++b) q[a][b] = cd(0, 0);
    const double is2 = 1.0 / std::sqrt(2.0);
    for (int m = -l; m < 0; ++m) {
        q[l + m][l - m] = cd(is2, 0.0);
        q[l + m][l + m] = cd(0.0, -is2);
    }
    q[l][l] = cd(1.0, 0.0);
    for (int m = 1; m <= l; ++m) {
        double sg = (m & 1) ? -1.0 : 1.0;
        q[l + m][l + m] = cd(sg * is2, 0.0);
        q[l + m][l - m] = cd(0.0, sg * is2);
    }
    cd ph;
    switch (l & 3) {
        case 0: ph = cd( 1,  0); break;
        case 1: ph = cd( 0, -1); break;
        case 2: ph = cd(-1,  0); break;
        default: ph = cd(0,  1); break;
    }
    for (int a = 0; a < 2 * l + 1; ++a) for (int b = 0; b < 2 * l + 1; ++b) q[a][b] *= ph;
}

static void wig3j(int l1, int l2, int l3, float* out) {
    const int d1 = 2 * l1 + 1, d2 = 2 * l2 + 1, d3 = 2 * l3 + 1;
    cd Q1[5][5], Q2[5][5], Q3[5][5];
    qmat(l1, Q1); qmat(l2, Q2); qmat(l3, Q3);
    static cd Csu2[5][5][5];
    for (int i = 0; i < d1; ++i)
        for (int k = 0; k < d2; ++k)
            for (int n = 0; n < d3; ++n)
                Csu2[i][k][n] = cd(su2_cg(l1, i - l1, l2, k - l2, l3, n - l3), 0.0);
    static double Cr[5][5][5];
    double nrm = 0.0;
    for (int j = 0; j < d1; ++j)
        for (int ll = 0; ll < d2; ++ll)
            for (int m = 0; m < d3; ++m) {
                cd acc(0, 0);
                for (int i = 0; i < d1; ++i)
                    for (int k = 0; k < d2; ++k)
                        for (int n = 0; n < d3; ++n)
                            acc += Q1[i][j] * Q2[k][ll] * std::conj(Q3[n][m]) * Csu2[i][k][n];
                Cr[j][ll][m] = acc.real();
                nrm += acc.real() * acc.real();
            }
    nrm = std::sqrt(nrm);
    int idx = 0;
    for (int j = 0; j < d1; ++j)
        for (int ll = 0; ll < d2; ++ll)
            for (int m = 0; m < d3; ++m)
                out[idx++] = (float)(Cr[j][ll][m] / nrm);
}

static void build(W3J& P) {
    float c220[25], c121[45], c112[45];
    wig3j(2, 2, 0, c220);
    wig3j(1, 2, 1, c121);
    wig3j(1, 1, 2, c112);
    const float a121 = std::sqrt(3.0f), a112 = std::sqrt(5.0f);
    for (int i = 0; i < 25; ++i) P.w220[i] = c220[i];
    for (int i = 0; i < 45; ++i) P.w121[i] = a121 * c121[i];
    for (int i = 0; i < 45; ++i) P.w112[i] = a112 * c112[i];
}
} // namespace hw3j

// ----------------------------------------------------------------------------
// bf16 split + mma + ldmatrix + cp.async helpers
// ----------------------------------------------------------------------------
__device__ __forceinline__ unsigned pack_bf16(float e0, float e1) {
    unsigned r;
    asm("cvt.rn.bf16x2.f32 %0, %1, %2;" : "=r"(r) : "f"(e1), "f"(e0));
    return r;
}
__device__ __forceinline__ void split_pair(float e0, float e1, unsigned& hi, unsigned& lo) {
    hi = pack_bf16(e0, e1);
    const float h0 = __uint_as_float(hi << 16);
    const float h1 = __uint_as_float(hi & 0xffff0000u);
    lo = pack_bf16(e0 - h0, e1 - h1);
}
__device__ __forceinline__ void mma16(float* d, const unsigned (&a)[4], const unsigned (&b)[2]) {
    asm("mma.sync.aligned.m16n8k16.row.col.f32.bf16.bf16.f32 "
        "{%0,%1,%2,%3}, {%4,%5,%6,%7}, {%8,%9}, {%0,%1,%2,%3};"
        : "+f"(d[0]), "+f"(d[1]), "+f"(d[2]), "+f"(d[3])
        : "r"(a[0]), "r"(a[1]), "r"(a[2]), "r"(a[3]), "r"(b[0]), "r"(b[1]));
}
__device__ __forceinline__ void ldsm_x4(unsigned (&a)[4], unsigned addr) {
    asm volatile("ldmatrix.sync.aligned.m8n8.x4.shared.b16 {%0,%1,%2,%3}, [%4];"
                 : "=r"(a[0]), "=r"(a[1]), "=r"(a[2]), "=r"(a[3]) : "r"(addr));
}
__device__ __forceinline__ void ldsm_x2(unsigned (&b)[2], unsigned addr) {
    asm volatile("ldmatrix.sync.aligned.m8n8.x2.shared.b16 {%0,%1}, [%2];"
                 : "=r"(b[0]), "=r"(b[1]) : "r"(addr));
}
__device__ __forceinline__ void cp16(unsigned dst_smem, const void* src) {
    asm volatile("cp.async.cg.shared.global [%0], [%1], 16;"
                 :: "r"(dst_smem), "l"(src) : "memory");
}
__device__ __forceinline__ void cp_commit() {
    asm volatile("cp.async.commit_group;" ::: "memory");
}
template<int N>
__device__ __forceinline__ void cp_wait() {
    asm volatile("cp.async.wait_group %0;" :: "n"(N) : "memory");
}

// ----------------------------------------------------------------------------
// Prologue: pre-split all weights into chunk-major g_wsplit
// ----------------------------------------------------------------------------
__global__ void split_weights_kernel(const float* __restrict__ Wl,
                                     const float* __restrict__ Wr,
                                     const float* __restrict__ Wf)
{
    const int tid = blockIdx.x * blockDim.x + threadIdx.x;   // < 73728
    const int slice = tid >> 13;          // 0..8
    const int p     = tid & 8191;
    const int mat   = slice / 3;          // 0=Wl 1=Wr 2=Wf
    const int l     = slice - mat * 3;
    const float* W = (mat == 0) ? Wl : (mat == 1) ? Wr : Wf;
    const int row = p >> 6;
    const int cp  = p & 63;               // word column 0..63
    const int kh  = cp >> 5;              // k-half
    const int c32 = cp & 31;              // word within chunk row
    const float e0 = W[(size_t)(l * 128 + row) * 128 + 2 * cp];
    const float e1 = W[(size_t)(l * 128 + row) * 128 + 2 * cp + 1];
    unsigned hi, lo;
    split_pair(e0, e1, hi, lo);
    unsigned off;
    if (mat == 2) off = GW_C0 + (l * 2 + kh) * GWC_C + row * 32 + c32;          // WFh part 0
    else          off = (l * 2 + kh) * GWC_A + mat * 8192 + row * 32 + c32;     // WLh / WRh
    g_wsplit[off]        = hi;
    g_wsplit[off + 4096] = lo;            // matching lo part
}

// ----------------------------------------------------------------------------
// Chunk compute (warp n-tile = 8). Interleaved L/R -> good chain distance.
// ----------------------------------------------------------------------------
#define PARTB (PART_W * 4)          // part stride, bytes = 18432

template<int L>
__device__ __forceinline__ void chunkA_mma(unsigned aab, unsigned bb, int khalf,
                                           float (&yL)[M_DIM][4], float (&yR)[M_DIM][4]) {
    constexpr int base = L * L;
    constexpr int msz  = 2 * L + 1;
    #pragma unroll
    for (int s = 0; s < 4; ++s) {
        unsigned bLh[2], bLl[2], bRh[2], bRl[2];
        const unsigned bo = bb + s * 32;
        ldsm_x2(bLh, bo);
        ldsm_x2(bLl, bo + PARTB);
        ldsm_x2(bRh, bo + 2 * PARTB);
        ldsm_x2(bRl, bo + 3 * PARTB);
        #pragma unroll
        for (int ml = 0; ml < msz; ++ml) {
            unsigned ah[4], al[4];
            const unsigned ao = aab + (base + ml) * (16 * 272) + (khalf * 4 + s) * 32;
            ldsm_x4(ah, ao + OFF_XH * 4);
            ldsm_x4(al, ao + OFF_XL * 4);
            mma16(yL[base + ml], ah, bLh);
            mma16(yR[base + ml], ah, bRh);
            mma16(yL[base + ml], ah, bLl);
            mma16(yR[base + ml], ah, bRl);
            mma16(yL[base + ml], al, bLh);
            mma16(yR[base + ml], al, bRh);
        }
    }
}

template<int L>
__device__ __forceinline__ void chunkC_mma(unsigned aab, unsigned bb, int khalf,
                                           float (&fo)[M_DIM][4]) {
    constexpr int base = L * L;
    constexpr int msz  = 2 * L + 1;
    #pragma unroll
    for (int s = 0; s < 4; ++s) {
        unsigned bh[2], blo[2];
        const unsigned bo = bb + s * 32;
        ldsm_x2(bh,  bo);
        ldsm_x2(blo, bo + PARTB);
        #pragma unroll
        for (int ml = 0; ml < msz; ++ml) {
            unsigned ah[4], al[4];
            const unsigned ao = aab + (base + ml) * (16 * 272) + (khalf * 4 + s) * 32;
            ldsm_x4(ah, ao + OFF_XH * 4);
            ldsm_x4(al, ao + OFF_XL * 4);
            mma16(fo[base + ml], ah, bh);
            mma16(fo[base + ml], ah, blo);
            mma16(fo[base + ml], al, bh);
        }
    }
}

// CG tensor product for one (node, channel)
__device__ __forceinline__ void tp_compute(const float (&L)[M_DIM], const float (&R)[M_DIM],
                                           float (&t)[M_DIM], const W3J& P) {
    {   // (2,2,0)
        float v = 0.f;
        #pragma unroll
        for (int i = 0; i < 5; ++i)
            #pragma unroll
            for (int j = 0; j < 5; ++j)
                v = fmaf(P.w220[i * 5 + j], L[4 + i] * R[4 + j], v);
        t[0] = v;
    }
    #pragma unroll
    for (int k = 0; k < 3; ++k) {   // (1,2,1)
        float v = 0.f;
        #pragma unroll
        for (int i = 0; i < 3; ++i)
            #pragma unroll
            for (int j = 0; j < 5; ++j)
                v = fmaf(P.w121[(i * 5 + j) * 3 + k], L[1 + i] * R[4 + j], v);
        t[1 + k] = v;
    }
    #pragma unroll
    for (int k = 0; k < 5; ++k) {   // (1,1,2)
        float v = 0.f;
        #pragma unroll
        for (int i = 0; i < 3; ++i)
            #pragma unroll
            for (int j = 0; j < 3; ++j)
                v = fmaf(P.w112[(i * 3 + j) * 5 + k], L[1 + i] * R[1 + j], v);
        t[4 + k] = v;
    }
}

// ----------------------------------------------------------------------------
// Fused kernel. 512 threads = 16 warps; warp wq owns channels [8wq, 8wq+8).
// Warp-PRIVATE weight pipelines (each warp copies/waits only its own 8 weight
// rows per chunk). Block barriers only at x-ready / pre-TP / post-TP.
// ----------------------------------------------------------------------------
__global__ __launch_bounds__(THREADS, 1)
void b2i_bf16x3_kernel(const float* __restrict__ x,
                       const float* __restrict__ bl,
                       const float* __restrict__ br,
                       const float* __restrict__ bf,
                       float* __restrict__ out, const W3J P)
{
    extern __shared__ unsigned sm[];

    const int tid  = threadIdx.x;
    const int lane = tid & 31;
    const int wq   = tid >> 5;            // 0..15: channel 8-block
    const int g    = lane >> 2;
    const int tg   = lane & 3;
    const size_t node0 = (size_t)blockIdx.x * B_NODES;

    const unsigned smb = (unsigned)__cvta_generic_to_shared(sm);
    const unsigned aab = smb + (((lane & 7) + ((lane >> 3) & 1) * 8) * XSTRIDE
                                + (lane >> 4) * 4) * 4;
    // B lane base within a weight buffer (byte offset, excl. buffer base)
    const unsigned bwb = ((lane & 7) * WSTRIDE + ((lane >> 3) & 1) * 4) * 4
                       + (8 * wq) * WSTRIDE * 4;

    // warp-private prefetch: copy THIS warp's 8 rows of chunk into slot chunk&1
    auto prefetchW = [&](int chunk) {
        const bool isA = chunk < 6;
        const unsigned* gsrc = g_wsplit + (isA ? chunk * GWC_A
                                              : GW_C0 + (chunk - 6) * GWC_C);
        const int ni = isA ? 8 : 4;         // float4s per lane (4 or 2 parts)
        const unsigned dbase = WBUF0 + (chunk & 1) * WBUF_WORDS;
        for (int i = 0; i < ni; ++i) {
            const int idx  = lane + i * 32;     // float4 index within warp slice
            const int part = idx >> 6;          // 64 float4 per part-slice
            const int r    = 8 * wq + ((idx >> 3) & 7);
            const int c4   = idx & 7;
            cp16(smb + (dbase + part * PART_W + r * WSTRIDE + c4 * 4) * 4,
                 gsrc + part * 4096 + r * 32 + c4 * 4);
        }
        cp_commit();
    };

    // prime the per-warp pipeline (depth 2)
    prefetchW(0);
    prefetchW(1);

    // ---- stage + split x tile: [node][m][c] -> rows (m*16+node), hi/lo words ----
    {
        #pragma unroll
        for (int i = 0; i < 9; ++i) {
            const int idx = tid + i * THREADS;     // 0..4607 float4s
            const int row = idx >> 5;              // node*9+m
            const int c4  = idx & 31;
            const int node = (row * 57) >> 9;      // row/9 for row<144
            const int m    = row - node * 9;
            const float4 v = __ldg(reinterpret_cast<const float4*>(
                x + ((node0 + node) * M_DIM + m) * C_DIM + c4 * 4));
            unsigned h0, l0, h1, l1;
            split_pair(v.x, v.y, h0, l0);
            split_pair(v.z, v.w, h1, l1);
            const int w = (m * 16 + node) * XSTRIDE + c4 * 2;
            *reinterpret_cast<uint2*>(sm + OFF_XH + w) = make_uint2(h0, h1);
            *reinterpret_cast<uint2*>(sm + OFF_XL + w) = make_uint2(l0, l1);
        }
    }
    __syncthreads();   // x tile ready for all warps

    float yL[M_DIM][4], yR[M_DIM][4];
    #pragma unroll
    for (int m = 0; m < M_DIM; ++m)
        #pragma unroll
        for (int c = 0; c < 4; ++c) { yL[m][c] = 0.f; yR[m][c] = 0.f; }

    #define BB(i) (smb + (WBUF0 + ((i) & 1) * WBUF_WORDS) * 4 + bwb)
    // per-warp chunk step: wait own copy, compute, issue copy for chunk+2
    #define CHUNKW(i, WN, BODY)                    \
        do {                                       \
            cp_wait<WN>();                         \
            __syncwarp();                          \
            BODY;                                  \
            if ((i) + 2 <= 11) prefetchW((i) + 2); \
        } while (0)

    // ---- stage A: 6 chunks (l, khalf), Wl+Wr fused; no block barriers ----
    CHUNKW(0, 1, chunkA_mma<0>(aab, BB(0), 0, yL, yR));
    CHUNKW(1, 1, chunkA_mma<0>(aab, BB(1), 1, yL, yR));
    CHUNKW(2, 1, chunkA_mma<1>(aab, BB(2), 0, yL, yR));
    CHUNKW(3, 1, chunkA_mma<1>(aab, BB(3), 1, yL, yR));
    CHUNKW(4, 1, chunkA_mma<2>(aab, BB(4), 0, yL, yR));
    CHUNKW(5, 1, chunkA_mma<2>(aab, BB(5), 1, yL, yR));

    __syncthreads();   // all warps' stage-A reads of x done before t overwrite

    // ---- stage B: thread-local tensor product; t split -> x region ----
    {
        const int ch0 = 8 * wq + 2 * tg;
        const int cw  = ch0 >> 1;
        const float bl0 = bl[ch0], bl1 = bl[ch0 + 1];
        const float br0 = br[ch0], br1 = br[ch0 + 1];

        float La[M_DIM], Ra[M_DIM], Lb[M_DIM], Rb[M_DIM], ta[M_DIM], tb[M_DIM];

        // node g  (frag cols 0,1)
        #pragma unroll
        for (int m = 0; m < M_DIM; ++m) {
            La[m] = yL[m][0]; Ra[m] = yR[m][0];
            Lb[m] = yL[m][1]; Rb[m] = yR[m][1];
        }
        La[0] += bl0; Ra[0] += br0; Lb[0] += bl1; Rb[0] += br1;
        tp_compute(La, Ra, ta, P);
        tp_compute(Lb, Rb, tb, P);
        #pragma unroll
        for (int m = 0; m < M_DIM; ++m) {
            unsigned h, lo;
            split_pair(ta[m], tb[m], h, lo);
            const int w = (m * 16 + g) * XSTRIDE + cw;
            sm[OFF_XH + w] = h; sm[OFF_XL + w] = lo;
        }

        // node g+8  (frag cols 2,3)
        #pragma unroll
        for (int m = 0; m < M_DIM; ++m) {
            La[m] = yL[m][2]; Ra[m] = yR[m][2];
            Lb[m] = yL[m][3]; Rb[m] = yR[m][3];
        }
        La[0] += bl0; Ra[0] += br0; Lb[0] += bl1; Rb[0] += br1;
        tp_compute(La, Ra, ta, P);
        tp_compute(Lb, Rb, tb, P);
        #pragma unroll
        for (int m = 0; m < M_DIM; ++m) {
            unsigned h, lo;
            split_pair(ta[m], tb[m], h, lo);
            const int w = (m * 16 + g + 8) * XSTRIDE + cw;
            sm[OFF_XH + w] = h; sm[OFF_XL + w] = lo;
        }
    }
    __syncthreads();   // t tile ready for all warps

    // ---- stage C: 6 chunks (l, khalf); warp-private pipeline continues ----
    float fo[M_DIM][4];
    #pragma unroll
    for (int m = 0; m < M_DIM; ++m)
        #pragma unroll
        for (int c = 0; c < 4; ++c) fo[m][c] = 0.f;

    CHUNKW(6,  1, chunkC_mma<0>(aab, BB(6),  0, fo));
    CHUNKW(7,  1, chunkC_mma<0>(aab, BB(7),  1, fo));
    CHUNKW(8,  1, chunkC_mma<1>(aab, BB(8),  0, fo));
    CHUNKW(9,  1, chunkC_mma<1>(aab, BB(9),  1, fo));
    CHUNKW(10, 1, chunkC_mma<2>(aab, BB(10), 0, fo));
    CHUNKW(11, 0, chunkC_mma<2>(aab, BB(11), 1, fo));

    #undef CHUNKW
    #undef BB

    // ---- bias + write out ----
    {
        const int ch0 = 8 * wq + 2 * tg;
        const float bf0 = bf[ch0], bf1 = bf[ch0 + 1];
        #pragma unroll
        for (int m = 0; m < M_DIM; ++m) {
            float v0 = fo[m][0], v1 = fo[m][1], v2 = fo[m][2], v3 = fo[m][3];
            if (m == 0) { v0 += bf0; v1 += bf1; v2 += bf0; v3 += bf1; }
            const size_t nA = node0 + g;
            const size_t nB = node0 + g + 8;
            *reinterpret_cast<float2*>(out + (nA * M_DIM + m) * C_DIM + ch0) =
                make_float2(v0, v1);
            *reinterpret_cast<float2*>(out + (nB * M_DIM + m) * C_DIM + ch0) =
                make_float2(v2, v3);
        }
    }
}

// ----------------------------------------------------------------------------
// Launch
// ----------------------------------------------------------------------------
extern "C" void kernel_launch(void* const* d_in, const int* in_sizes, int n_in,
                              void* d_out, int out_size)
{
    const float* x  = (const float*)d_in[0];
    const float* Wl = (const float*)d_in[1];
    const float* bl = (const float*)d_in[2];
    const float* Wr = (const float*)d_in[3];
    const float* br = (const float*)d_in[4];
    const float* Wf = (const float*)d_in[5];
    const float* bf = (const float*)d_in[6];
    float* out = (float*)d_out;

    W3J P;
    hw3j::build(P);

    split_weights_kernel<<<288, 256>>>(Wl, Wr, Wf);

    cudaFuncSetAttribute(b2i_bf16x3_kernel, cudaFuncAttributeMaxDynamicSharedMemorySize, SMEM_BYTES);
    b2i_bf16x3_kernel<<<NNODES / B_NODES, THREADS, SMEM_BYTES>>>(
        x, bl, br, bf, out, P);
}

// round 16
// speedup vs baseline: 1.0650x; 1.0650x over previous
#include <cuda_runtime.h>
#include <cmath>
#include <complex>
#include <algorithm>

// ----------------------------------------------------------------------------
// Problem constants
// ----------------------------------------------------------------------------
#define NNODES   50000
#define C_DIM    128
#define M_DIM    9
#define B_NODES  16
#define THREADS  256

// x region (b32 = bf16x2 words)
#define XSTRIDE  68                        // row stride words (==4 mod 32), 272 B
#define SXW      (144 * XSTRIDE)           // 9792 words per x part (hi / lo)
#define OFF_XH   0
#define OFF_XL   (SXW)

// weight chunk buffers: stride 36 words (144 B, ==4 mod 32, 16B-aligned rows)
#define WSTRIDE  36
#define PART_W   (128 * WSTRIDE)           // 4608 words per part
#define WBUF_WORDS (4 * PART_W)            // 18432 words (A chunks use 4 parts)
#define WBUF0    (2 * SXW)                 // 19584
#define SMEM_WORDS (2 * SXW + 2 * WBUF_WORDS)  // 56448 words
#define SMEM_BYTES (SMEM_WORDS * 4)            // 225792 B

// Pre-split weight scratch, chunk-major:
//  A chunks 0..5  = (l, khalf): 16384 words = [part: WLh,WLl,WRh,WRl][row 128][32]
//  C chunks 6..11 = (l, khalf):  8192 words = [part: WFh,WFl][row 128][32]
#define GWC_A    16384
#define GWC_C    8192
#define GW_C0    (6 * GWC_A)               // 98304
#define GW_WORDS 147456
__device__ __align__(16) unsigned g_wsplit[GW_WORDS];

// Wigner-3j tables (alpha folded in), kernel arg.
struct W3J {
    float w220[25];
    float w121[45];
    float w112[45];
};

// ----------------------------------------------------------------------------
// Host-side Wigner 3j (literal translation of the reference, double precision)
// ----------------------------------------------------------------------------
namespace hw3j {
typedef std::complex<double> cd;

static inline double fact(int n) { double r = 1.0; for (int i = 2; i <= n; ++i) r *= (double)i; return r; }

static double su2_cg(int j1, int m1, int j2, int m2, int j3, int m3) {
    if (m1 + m2 != m3) return 0.0;
    int vmin = std::max(std::max(-j1 + j2 + m3, -j1 + m1), 0);
    int vmax = std::min(std::min(j2 + j3 + m1, j3 - j1 + j2), j3 + m3);
    double pref = std::sqrt((2.0 * j3 + 1.0)
        * fact(j3 + j1 - j2) * fact(j3 - j1 + j2) * fact(j1 + j2 - j3) / fact(j1 + j2 + j3 + 1)
        * fact(j3 + m3) * fact(j3 - m3)
        / (fact(j1 - m1) * fact(j1 + m1) * fact(j2 - m2) * fact(j2 + m2)));
    double s = 0.0;
    for (int v = vmin; v <= vmax; ++v) {
        double sgn = ((v + j2 + m2) & 1) ? -1.0 : 1.0;
        s += sgn / fact(v) * fact(j2 + j3 + m1 - v) * fact(j1 - m1 + v)
             / (fact(j3 - j1 + j2 - v) * fact(j3 + m3 - v) * fact(v + j1 - j2 - m3));
    }
    return pref * s;
}

static void qmat(int l, cd q[5][5]) {
    for (int a = 0; a < 5; ++a) for (int b = 0; b < 5; ++b) q[a][b] = cd(0, 0);
    const double is2 = 1.0 / std::sqrt(2.0);
    for (int m = -l; m < 0; ++m) {
        q[l + m][l - m] = cd(is2, 0.0);
        q[l + m][l + m] = cd(0.0, -is2);
    }
    q[l][l] = cd(1.0, 0.0);
    for (int m = 1; m <= l; ++m) {
        double sg = (m & 1) ? -1.0 : 1.0;
        q[l + m][l + m] = cd(sg * is2, 0.0);
        q[l + m][l - m] = cd(0.0, sg * is2);
    }
    cd ph;
    switch (l & 3) {
        case 0: ph = cd( 1,  0); break;
        case 1: ph = cd( 0, -1); break;
        case 2: ph = cd(-1,  0); break;
        default: ph = cd(0,  1); break;
    }
    for (int a = 0; a < 2 * l + 1; ++a) for (int b = 0; b < 2 * l + 1; ++b) q[a][b] *= ph;
}

static void wig3j(int l1, int l2, int l3, float* out) {
    const int d1 = 2 * l1 + 1, d2 = 2 * l2 + 1, d3 = 2 * l3 + 1;
    cd Q1[5][5], Q2[5][5], Q3[5][5];
    qmat(l1, Q1); qmat(l2, Q2); qmat(l3, Q3);
    static cd Csu2[5][5][5];
    for (int i = 0; i < d1; ++i)
        for (int k = 0; k < d2; ++k)
            for (int n = 0; n < d3; ++n)
                Csu2[i][k][n] = cd(su2_cg(l1, i - l1, l2, k - l2, l3, n - l3), 0.0);
    static double Cr[5][5][5];
    double nrm = 0.0;
    for (int j = 0; j < d1; ++j)
        for (int ll = 0; ll < d2; ++ll)
            for (int m = 0; m < d3; ++m) {
                cd acc(0, 0);
                for (int i = 0; i < d1; ++i)
                    for (int k = 0; k < d2; ++k)
                        for (int n = 0; n < d3; ++n)
                            acc += Q1[i][j] * Q2[k][ll] * std::conj(Q3[n][m]) * Csu2[i][k][n];
                Cr[j][ll][m] = acc.real();
                nrm += acc.real() * acc.real();
            }
    nrm = std::sqrt(nrm);
    int idx = 0;
    for (int j = 0; j < d1; ++j)
        for (int ll = 0; ll < d2; ++ll)
            for (int m = 0; m < d3; ++m)
                out[idx++] = (float)(Cr[j][ll][m] / nrm);
}

static void build(W3J& P) {
    float c220[25], c121[45], c112[45];
    wig3j(2, 2, 0, c220);
    wig3j(1, 2, 1, c121);
    wig3j(1, 1, 2, c112);
    const float a121 = std::sqrt(3.0f), a112 = std::sqrt(5.0f);
    for (int i = 0; i < 25; ++i) P.w220[i] = c220[i];
    for (int i = 0; i < 45; ++i) P.w121[i] = a121 * c121[i];
    for (int i = 0; i < 45; ++i) P.w112[i] = a112 * c112[i];
}
} // namespace hw3j

// ----------------------------------------------------------------------------
// bf16 split + mma + ldmatrix + cp.async helpers
// ----------------------------------------------------------------------------
__device__ __forceinline__ unsigned pack_bf16(float e0, float e1) {
    unsigned r;
    asm("cvt.rn.bf16x2.f32 %0, %1, %2;" : "=r"(r) : "f"(e1), "f"(e0));
    return r;
}
__device__ __forceinline__ void split_pair(float e0, float e1, unsigned& hi, unsigned& lo) {
    hi = pack_bf16(e0, e1);
    const float h0 = __uint_as_float(hi << 16);
    const float h1 = __uint_as_float(hi & 0xffff0000u);
    lo = pack_bf16(e0 - h0, e1 - h1);
}
__device__ __forceinline__ void mma16(float* d, const unsigned* a, const unsigned (&b)[2]) {
    asm("mma.sync.aligned.m16n8k16.row.col.f32.bf16.bf16.f32 "
        "{%0,%1,%2,%3}, {%4,%5,%6,%7}, {%8,%9}, {%0,%1,%2,%3};"
        : "+f"(d[0]), "+f"(d[1]), "+f"(d[2]), "+f"(d[3])
        : "r"(a[0]), "r"(a[1]), "r"(a[2]), "r"(a[3]), "r"(b[0]), "r"(b[1]));
}
__device__ __forceinline__ void ldsm_x4(unsigned* a, unsigned addr) {
    asm volatile("ldmatrix.sync.aligned.m8n8.x4.shared.b16 {%0,%1,%2,%3}, [%4];"
                 : "=r"(a[0]), "=r"(a[1]), "=r"(a[2]), "=r"(a[3]) : "r"(addr));
}
__device__ __forceinline__ void ldsm_x2(unsigned (&b)[2], unsigned addr) {
    asm volatile("ldmatrix.sync.aligned.m8n8.x2.shared.b16 {%0,%1}, [%2];"
                 : "=r"(b[0]), "=r"(b[1]) : "r"(addr));
}
__device__ __forceinline__ void cp16(unsigned dst_smem, const void* src) {
    asm volatile("cp.async.cg.shared.global [%0], [%1], 16;"
                 :: "r"(dst_smem), "l"(src) : "memory");
}
__device__ __forceinline__ void cp_commit() {
    asm volatile("cp.async.commit_group;" ::: "memory");
}
template<int N>
__device__ __forceinline__ void cp_wait() {
    asm volatile("cp.async.wait_group %0;" :: "n"(N) : "memory");
}

// ----------------------------------------------------------------------------
// Prologue: pre-split all weights into chunk-major g_wsplit
// ----------------------------------------------------------------------------
__global__ void split_weights_kernel(const float* __restrict__ Wl,
                                     const float* __restrict__ Wr,
                                     const float* __restrict__ Wf)
{
    const int tid = blockIdx.x * blockDim.x + threadIdx.x;   // < 73728
    const int slice = tid >> 13;          // 0..8
    const int p     = tid & 8191;
    const int mat   = slice / 3;          // 0=Wl 1=Wr 2=Wf
    const int l     = slice - mat * 3;
    const float* W = (mat == 0) ? Wl : (mat == 1) ? Wr : Wf;
    const int row = p >> 6;
    const int cp  = p & 63;               // word column 0..63
    const int kh  = cp >> 5;              // k-half
    const int c32 = cp & 31;              // word within chunk row
    const float e0 = W[(size_t)(l * 128 + row) * 128 + 2 * cp];
    const float e1 = W[(size_t)(l * 128 + row) * 128 + 2 * cp + 1];
    unsigned hi, lo;
    split_pair(e0, e1, hi, lo);
    unsigned off;
    if (mat == 2) off = GW_C0 + (l * 2 + kh) * GWC_C + row * 32 + c32;          // WFh part 0
    else          off = (l * 2 + kh) * GWC_A + mat * 8192 + row * 32 + c32;     // WLh / WRh
    g_wsplit[off]        = hi;
    g_wsplit[off + 4096] = lo;            // matching lo part
}

// ----------------------------------------------------------------------------
// Chunk compute (n=16 per warp). Pass-major MMA ordering: all fragment loads
// hoisted per k-step; each accumulator re-touched only once per pass
// (chain distance 4*msz) to cover HMMA accumulate latency.
// ----------------------------------------------------------------------------
#define PARTB (PART_W * 4)          // part stride, bytes = 18432
#define JROWB (8 * WSTRIDE * 4)     // 8 n-rows, bytes = 1152

template<int L>
__device__ __forceinline__ void chunkA_mma(unsigned aab, unsigned bb, int khalf,
                                           float (&yL)[M_DIM][2][4], float (&yR)[M_DIM][2][4]) {
    constexpr int base = L * L;
    constexpr int msz  = 2 * L + 1;
    #pragma unroll
    for (int s = 0; s < 4; ++s) {
        // ---- hoisted fragment loads ----
        unsigned bLh[2][2], bLl[2][2], bRh[2][2], bRl[2][2];
        #pragma unroll
        for (int j = 0; j < 2; ++j) {
            const unsigned bo = bb + j * JROWB + s * 32;
            ldsm_x2(bLh[j], bo);
            ldsm_x2(bLl[j], bo + PARTB);
            ldsm_x2(bRh[j], bo + 2 * PARTB);
            ldsm_x2(bRl[j], bo + 3 * PARTB);
        }
        unsigned ah[msz][4], al[msz][4];
        #pragma unroll
        for (int ml = 0; ml < msz; ++ml) {
            const unsigned ao = aab + (base + ml) * (16 * 272) + (khalf * 4 + s) * 32;
            ldsm_x4(ah[ml], ao + OFF_XH * 4);
            ldsm_x4(al[ml], ao + OFF_XL * 4);
        }
        // ---- pass 1: ah x bh ----
        #pragma unroll
        for (int j = 0; j < 2; ++j)
            #pragma unroll
            for (int ml = 0; ml < msz; ++ml) {
                mma16(yL[base + ml][j], ah[ml], bLh[j]);
                mma16(yR[base + ml][j], ah[ml], bRh[j]);
            }
        // ---- pass 2: ah x bl ----
        #pragma unroll
        for (int j = 0; j < 2; ++j)
            #pragma unroll
            for (int ml = 0; ml < msz; ++ml) {
                mma16(yL[base + ml][j], ah[ml], bLl[j]);
                mma16(yR[base + ml][j], ah[ml], bRl[j]);
            }
        // ---- pass 3: al x bh ----
        #pragma unroll
        for (int j = 0; j < 2; ++j)
            #pragma unroll
            for (int ml = 0; ml < msz; ++ml) {
                mma16(yL[base + ml][j], al[ml], bLh[j]);
                mma16(yR[base + ml][j], al[ml], bRh[j]);
            }
    }
}

template<int L>
__device__ __forceinline__ void chunkC_mma(unsigned aab, unsigned bb, int khalf,
                                           float (&fo)[M_DIM][2][4]) {
    constexpr int base = L * L;
    constexpr int msz  = 2 * L + 1;
    #pragma unroll
    for (int s = 0; s < 4; ++s) {
        unsigned bh[2][2], blo[2][2];
        #pragma unroll
        for (int j = 0; j < 2; ++j) {
            const unsigned bo = bb + j * JROWB + s * 32;
            ldsm_x2(bh[j],  bo);
            ldsm_x2(blo[j], bo + PARTB);
        }
        unsigned ah[msz][4], al[msz][4];
        #pragma unroll
        for (int ml = 0; ml < msz; ++ml) {
            const unsigned ao = aab + (base + ml) * (16 * 272) + (khalf * 4 + s) * 32;
            ldsm_x4(ah[ml], ao + OFF_XH * 4);
            ldsm_x4(al[ml], ao + OFF_XL * 4);
        }
        #pragma unroll
        for (int j = 0; j < 2; ++j)
            #pragma unroll
            for (int ml = 0; ml < msz; ++ml)
                mma16(fo[base + ml][j], ah[ml], bh[j]);
        #pragma unroll
        for (int j = 0; j < 2; ++j)
            #pragma unroll
            for (int ml = 0; ml < msz; ++ml)
                mma16(fo[base + ml][j], ah[ml], blo[j]);
        #pragma unroll
        for (int j = 0; j < 2; ++j)
            #pragma unroll
            for (int ml = 0; ml < msz; ++ml)
                mma16(fo[base + ml][j], al[ml], bh[j]);
    }
}

// CG tensor product for one (node, channel)
__device__ __forceinline__ void tp_compute(const float (&L)[M_DIM], const float (&R)[M_DIM],
                                           float (&t)[M_DIM], const W3J& P) {
    {   // (2,2,0)
        float v = 0.f;
        #pragma unroll
        for (int i = 0; i < 5; ++i)
            #pragma unroll
            for (int j = 0; j < 5; ++j)
                v = fmaf(P.w220[i * 5 + j], L[4 + i] * R[4 + j], v);
        t[0] = v;
    }
    #pragma unroll
    for (int k = 0; k < 3; ++k) {   // (1,2,1)
        float v = 0.f;
        #pragma unroll
        for (int i = 0; i < 3; ++i)
            #pragma unroll
            for (int j = 0; j < 5; ++j)
                v = fmaf(P.w121[(i * 5 + j) * 3 + k], L[1 + i] * R[4 + j], v);
        t[1 + k] = v;
    }
    #pragma unroll
    for (int k = 0; k < 5; ++k) {   // (1,1,2)
        float v = 0.f;
        #pragma unroll
        for (int i = 0; i < 3; ++i)
            #pragma unroll
            for (int j = 0; j < 3; ++j)
                v = fmaf(P.w112[(i * 3 + j) * 5 + k], L[1 + i] * R[1 + j], v);
        t[4 + k] = v;
    }
}

// ----------------------------------------------------------------------------
// Fused kernel. 256 threads = 8 warps; warp wq owns channels [16wq, 16wq+16).
// Warp-PRIVATE weight pipelines; block barriers only at x-ready/pre-TP/post-TP.
// ----------------------------------------------------------------------------
__global__ __launch_bounds__(THREADS, 1)
void b2i_bf16x3_kernel(const float* __restrict__ x,
                       const float* __restrict__ bl,
                       const float* __restrict__ br,
                       const float* __restrict__ bf,
                       float* __restrict__ out, const W3J P)
{
    extern __shared__ unsigned sm[];

    const int tid  = threadIdx.x;
    const int lane = tid & 31;
    const int wq   = tid >> 5;
    const int g    = lane >> 2;
    const int tg   = lane & 3;
    const size_t node0 = (size_t)blockIdx.x * B_NODES;

    const unsigned smb = (unsigned)__cvta_generic_to_shared(sm);
    const unsigned aab = smb + (((lane & 7) + ((lane >> 3) & 1) * 8) * XSTRIDE
                                + (lane >> 4) * 4) * 4;
    // B lane base within a weight buffer (byte offset, excl. buffer base)
    const unsigned bwb = ((lane & 7) * WSTRIDE + ((lane >> 3) & 1) * 4) * 4
                       + (16 * wq) * WSTRIDE * 4;

    // warp-private prefetch: copy THIS warp's 16 rows of chunk into slot chunk&1
    auto prefetchW = [&](int chunk) {
        const bool isA = chunk < 6;
        const unsigned* gsrc = g_wsplit + (isA ? chunk * GWC_A
                                              : GW_C0 + (chunk - 6) * GWC_C);
        const int ni = isA ? 16 : 8;        // float4s per lane (4 or 2 parts)
        const unsigned dbase = WBUF0 + (chunk & 1) * WBUF_WORDS;
        for (int i = 0; i < ni; ++i) {
            const int idx  = lane + i * 32;     // float4 index within warp slice
            const int part = idx >> 7;          // 128 float4 per part-slice
            const int r    = 16 * wq + ((idx >> 3) & 15);
            const int c4   = idx & 7;
            cp16(smb + (dbase + part * PART_W + r * WSTRIDE + c4 * 4) * 4,
                 gsrc + part * 4096 + r * 32 + c4 * 4);
        }
        cp_commit();
    };

    // prime the per-warp pipeline (depth 2)
    prefetchW(0);
    prefetchW(1);

    // ---- stage + split x tile: [node][m][c] -> rows (m*16+node), hi/lo words ----
    {
        #pragma unroll
        for (int i = 0; i < 18; ++i) {
            const int idx = tid + i * THREADS;     // 0..4607 float4s
            const int row = idx >> 5;              // node*9+m
            const int c4  = idx & 31;
            const int node = (row * 57) >> 9;      // row/9 for row<144
            const int m    = row - node * 9;
            const float4 v = __ldg(reinterpret_cast<const float4*>(
                x + ((node0 + node) * M_DIM + m) * C_DIM + c4 * 4));
            unsigned h0, l0, h1, l1;
            split_pair(v.x, v.y, h0, l0);
            split_pair(v.z, v.w, h1, l1);
            const int w = (m * 16 + node) * XSTRIDE + c4 * 2;
            *reinterpret_cast<uint2*>(sm + OFF_XH + w) = make_uint2(h0, h1);
            *reinterpret_cast<uint2*>(sm + OFF_XL + w) = make_uint2(l0, l1);
        }
    }
    __syncthreads();   // x tile ready for all warps

    float yL[M_DIM][2][4], yR[M_DIM][2][4];
    #pragma unroll
    for (int m = 0; m < M_DIM; ++m)
        #pragma unroll
        for (int j = 0; j < 2; ++j)
            #pragma unroll
            for (int c = 0; c < 4; ++c) { yL[m][j][c] = 0.f; yR[m][j][c] = 0.f; }

    #define BB(i) (smb + (WBUF0 + ((i) & 1) * WBUF_WORDS) * 4 + bwb)
    // per-warp chunk step: wait own copy, compute, issue copy for chunk+2
    #define CHUNKW(i, WN, BODY)                    \
        do {                                       \
            cp_wait<WN>();                         \
            __syncwarp();                          \
            BODY;                                  \
            if ((i) + 2 <= 11) prefetchW((i) + 2); \
        } while (0)

    // ---- stage A: 6 chunks (l, khalf), Wl+Wr fused; no block barriers ----
    CHUNKW(0, 1, chunkA_mma<0>(aab, BB(0), 0, yL, yR));
    CHUNKW(1, 1, chunkA_mma<0>(aab, BB(1), 1, yL, yR));
    CHUNKW(2, 1, chunkA_mma<1>(aab, BB(2), 0, yL, yR));
    CHUNKW(3, 1, chunkA_mma<1>(aab, BB(3), 1, yL, yR));
    CHUNKW(4, 1, chunkA_mma<2>(aab, BB(4), 0, yL, yR));
    CHUNKW(5, 1, chunkA_mma<2>(aab, BB(5), 1, yL, yR));

    __syncthreads();   // all warps' stage-A reads of x done before t overwrite

    // ---- stage B: thread-local tensor product; t split -> x region ----
    #pragma unroll
    for (int j = 0; j < 2; ++j) {
        const int ch0 = 16 * wq + 8 * j + 2 * tg;
        const int cw  = ch0 >> 1;
        const float bl0 = bl[ch0], bl1 = bl[ch0 + 1];
        const float br0 = br[ch0], br1 = br[ch0 + 1];

        float La[M_DIM], Ra[M_DIM], Lb[M_DIM], Rb[M_DIM], ta[M_DIM], tb[M_DIM];

        // node g
        #pragma unroll
        for (int m = 0; m < M_DIM; ++m) {
            La[m] = yL[m][j][0]; Ra[m] = yR[m][j][0];
            Lb[m] = yL[m][j][1]; Rb[m] = yR[m][j][1];
        }
        La[0] += bl0; Ra[0] += br0; Lb[0] += bl1; Rb[0] += br1;
        tp_compute(La, Ra, ta, P);
        tp_compute(Lb, Rb, tb, P);
        #pragma unroll
        for (int m = 0; m < M_DIM; ++m) {
            unsigned h, lo;
            split_pair(ta[m], tb[m], h, lo);
            const int w = (m * 16 + g) * XSTRIDE + cw;
            sm[OFF_XH + w] = h; sm[OFF_XL + w] = lo;
        }

        // node g+8
        #pragma unroll
        for (int m = 0; m < M_DIM; ++m) {
            La[m] = yL[m][j][2]; Ra[m] = yR[m][j][2];
            Lb[m] = yL[m][j][3]; Rb[m] = yR[m][j][3];
        }
        La[0] += bl0; Ra[0] += br0; Lb[0] += bl1; Rb[0] += br1;
        tp_compute(La, Ra, ta, P);
        tp_compute(Lb, Rb, tb, P);
        #pragma unroll
        for (int m = 0; m < M_DIM; ++m) {
            unsigned h, lo;
            split_pair(ta[m], tb[m], h, lo);
            const int w = (m * 16 + g + 8) * XSTRIDE + cw;
            sm[OFF_XH + w] = h; sm[OFF_XL + w] = lo;
        }
    }
    __syncthreads();   // t tile ready for all warps

    // ---- stage C: 6 chunks (l, khalf); warp-private pipeline continues ----
    float fo[M_DIM][2][4];
    #pragma unroll
    for (int m = 0; m < M_DIM; ++m)
        #pragma unroll
        for (int j = 0; j < 2; ++j)
            #pragma unroll
            for (int c = 0; c < 4; ++c) fo[m][j][c] = 0.f;

    CHUNKW(6,  1, chunkC_mma<0>(aab, BB(6),  0, fo));
    CHUNKW(7,  1, chunkC_mma<0>(aab, BB(7),  1, fo));
    CHUNKW(8,  1, chunkC_mma<1>(aab, BB(8),  0, fo));
    CHUNKW(9,  1, chunkC_mma<1>(aab, BB(9),  1, fo));
    CHUNKW(10, 1, chunkC_mma<2>(aab, BB(10), 0, fo));
    CHUNKW(11, 0, chunkC_mma<2>(aab, BB(11), 1, fo));

    #undef CHUNKW
    #undef BB

    // ---- bias + write out ----
    #pragma unroll
    for (int j = 0; j < 2; ++j) {
        const int ch0 = 16 * wq + 8 * j + 2 * tg;
        const float bf0 = bf[ch0], bf1 = bf[ch0 + 1];
        #pragma unroll
        for (int m = 0; m < M_DIM; ++m) {
            float v0 = fo[m][j][0], v1 = fo[m][j][1], v2 = fo[m][j][2], v3 = fo[m][j][3];
            if (m == 0) { v0 += bf0; v1 += bf1; v2 += bf0; v3 += bf1; }
            const size_t nA = node0 + g;
            const size_t nB = node0 + g + 8;
            *reinterpret_cast<float2*>(out + (nA * M_DIM + m) * C_DIM + ch0) =
                make_float2(v0, v1);
            *reinterpret_cast<float2*>(out + (nB * M_DIM + m) * C_DIM + ch0) =
                make_float2(v2, v3);
        }
    }
}

// ----------------------------------------------------------------------------
// Launch
// ----------------------------------------------------------------------------
extern "C" void kernel_launch(void* const* d_in, const int* in_sizes, int n_in,
                              void* d_out, int out_size)
{
    const float* x  = (const float*)d_in[0];
    const float* Wl = (const float*)d_in[1];
    const float* bl = (const float*)d_in[2];
    const float* Wr = (const float*)d_in[3];
    const float* br = (const float*)d_in[4];
    const float* Wf = (const float*)d_in[5];
    const float* bf = (const float*)d_in[6];
    float* out = (float*)d_out;

    W3J P;
    hw3j::build(P);

    split_weights_kernel<<<288, 256>>>(Wl, Wr, Wf);

    cudaFuncSetAttribute(b2i_bf16x3_kernel, cudaFuncAttributeMaxDynamicSharedMemorySize, SMEM_BYTES);
    b2i_bf16x3_kernel<<<NNODES / B_NODES, THREADS, SMEM_BYTES>>>(
        x, bl, br, bf, out, P);
}

// round 17
// speedup vs baseline: 1.4464x; 1.3581x over previous
#include <cuda_runtime.h>
#include <cuda_fp16.h>
#include <cmath>
#include <complex>
#include <algorithm>

// ----------------------------------------------------------------------------
// Problem constants
// ----------------------------------------------------------------------------
#define NNODES   50000
#define C_DIM    128
#define M_DIM    9
#define B_NODES  16
#define THREADS  256

// x region (b32 = fp16x2 words)
#define XSTRIDE  68                        // row stride words (==4 mod 32), 272 B
#define SXW      (144 * XSTRIDE)           // 9792 words per x part (hi / lo)
#define OFF_XH   0
#define OFF_XL   (SXW)

// weight chunk buffers: stride 36 words (144 B, ==4 mod 32, 16B-aligned rows)
#define WSTRIDE  36
#define PART_W   (128 * WSTRIDE)           // 4608 words per part
#define WBUF_WORDS (2 * PART_W)            // 9216 words (A chunks: WL, WR parts)
#define WBUF0    (2 * SXW)                 // 19584
#define SMEM_WORDS (2 * SXW + 2 * WBUF_WORDS)  // 38016 words
#define SMEM_BYTES (SMEM_WORDS * 4)            // 152064 B

// Pre-split fp16 weight scratch, chunk-major:
//  A chunks 0..5  = (l, khalf): 8192 words = [part: WL, WR][row 128][32]
//  C chunks 6..11 = (l, khalf): 4096 words = [WF][row 128][32]
#define GWC_A    8192
#define GWC_C    4096
#define GW_C0    (6 * GWC_A)               // 49152
#define GW_WORDS 73728
__device__ __align__(16) unsigned g_wsplit[GW_WORDS];

// Wigner-3j tables (alpha folded in), kernel arg.
struct W3J {
    float w220[25];
    float w121[45];
    float w112[45];
};

// ----------------------------------------------------------------------------
// Host-side Wigner 3j (literal translation of the reference, double precision)
// ----------------------------------------------------------------------------
namespace hw3j {
typedef std::complex<double> cd;

static inline double fact(int n) { double r = 1.0; for (int i = 2; i <= n; ++i) r *= (double)i; return r; }

static double su2_cg(int j1, int m1, int j2, int m2, int j3, int m3) {
    if (m1 + m2 != m3) return 0.0;
    int vmin = std::max(std::max(-j1 + j2 + m3, -j1 + m1), 0);
    int vmax = std::min(std::min(j2 + j3 + m1, j3 - j1 + j2), j3 + m3);
    double pref = std::sqrt((2.0 * j3 + 1.0)
        * fact(j3 + j1 - j2) * fact(j3 - j1 + j2) * fact(j1 + j2 - j3) / fact(j1 + j2 + j3 + 1)
        * fact(j3 + m3) * fact(j3 - m3)
        / (fact(j1 - m1) * fact(j1 + m1) * fact(j2 - m2) * fact(j2 + m2)));
    double s = 0.0;
    for (int v = vmin; v <= vmax; ++v) {
        double sgn = ((v + j2 + m2) & 1) ? -1.0 : 1.0;
        s += sgn / fact(v) * fact(j2 + j3 + m1 - v) * fact(j1 - m1 + v)
             / (fact(j3 - j1 + j2 - v) * fact(j3 + m3 - v) * fact(v + j1 - j2 - m3));
    }
    return pref * s;
}

static void qmat(int l, cd q[5][5]) {
    for (int a = 0; a < 5; ++a) for (int b = 0; b < 5; ++b) q[a][b] = cd(0, 0);
    const double is2 = 1.0 / std::sqrt(2.0);
    for (int m = -l; m < 0; ++m) {
        q[l + m][l - m] = cd(is2, 0.0);
        q[l + m][l + m] = cd(0.0, -is2);
    }
    q[l][l] = cd(1.0, 0.0);
    for (int m = 1; m <= l; ++m) {
        double sg = (m & 1) ? -1.0 : 1.0;
        q[l + m][l + m] = cd(sg * is2, 0.0);
        q[l + m][l - m] = cd(0.0, sg * is2);
    }
    cd ph;
    switch (l & 3) {
        case 0: ph = cd( 1,  0); break;
        case 1: ph = cd( 0, -1); break;
        case 2: ph = cd(-1,  0); break;
        default: ph = cd(0,  1); break;
    }
    for (int a = 0; a < 2 * l + 1; ++a) for (int b = 0; b < 2 * l + 1; ++b) q[a][b] *= ph;
}

static void wig3j(int l1, int l2, int l3, float* out) {
    const int d1 = 2 * l1 + 1, d2 = 2 * l2 + 1, d3 = 2 * l3 + 1;
    cd Q1[5][5], Q2[5][5], Q3[5][5];
    qmat(l1, Q1); qmat(l2, Q2); qmat(l3, Q3);
    static cd Csu2[5][5][5];
    for (int i = 0; i < d1; ++i)
        for (int k = 0; k < d2; ++k)
            for (int n = 0; n < d3; ++n)
                Csu2[i][k][n] = cd(su2_cg(l1, i - l1, l2, k - l2, l3, n - l3), 0.0);
    static double Cr[5][5][5];
    double nrm = 0.0;
    for (int j = 0; j < d1; ++j)
        for (int ll = 0; ll < d2; ++ll)
            for (int m = 0; m < d3; ++m) {
                cd acc(0, 0);
                for (int i = 0; i < d1; ++i)
                    for (int k = 0; k < d2; ++k)
                        for (int n = 0; n < d3; ++n)
                            acc += Q1[i][j] * Q2[k][ll] * std::conj(Q3[n][m]) * Csu2[i][k][n];
                Cr[j][ll][m] = acc.real();
                nrm += acc.real() * acc.real();
            }
    nrm = std::sqrt(nrm);
    int idx = 0;
    for (int j = 0; j < d1; ++j)
        for (int ll = 0; ll < d2; ++ll)
            for (int m = 0; m < d3; ++m)
                out[idx++] = (float)(Cr[j][ll][m] / nrm);
}

static void build(W3J& P) {
    float c220[25], c121[45], c112[45];
    wig3j(2, 2, 0, c220);
    wig3j(1, 2, 1, c121);
    wig3j(1, 1, 2, c112);
    const float a121 = std::sqrt(3.0f), a112 = std::sqrt(5.0f);
    for (int i = 0; i < 25; ++i) P.w220[i] = c220[i];
    for (int i = 0; i < 45; ++i) P.w121[i] = a121 * c121[i];
    for (int i = 0; i < 45; ++i) P.w112[i] = a112 * c112[i];
}
} // namespace hw3j

// ----------------------------------------------------------------------------
// fp16 helpers + mma + ldmatrix + cp.async
// ----------------------------------------------------------------------------
__device__ __forceinline__ unsigned pack_f16(float e0, float e1) {
    __half2 h = __floats2half2_rn(e0, e1);
    return *reinterpret_cast<unsigned*>(&h);
}
// split pair into fp16 hi word + fp16 residual word
__device__ __forceinline__ void split_pair_f16(float e0, float e1, unsigned& hi, unsigned& lo) {
    __half2 h = __floats2half2_rn(e0, e1);
    hi = *reinterpret_cast<unsigned*>(&h);
    const float f0 = __low2float(h);
    const float f1 = __high2float(h);
    lo = pack_f16(e0 - f0, e1 - f1);
}
__device__ __forceinline__ void mma16(float* d, const unsigned (&a)[4], const unsigned (&b)[2]) {
    asm("mma.sync.aligned.m16n8k16.row.col.f32.f16.f16.f32 "
        "{%0,%1,%2,%3}, {%4,%5,%6,%7}, {%8,%9}, {%0,%1,%2,%3};"
        : "+f"(d[0]), "+f"(d[1]), "+f"(d[2]), "+f"(d[3])
        : "r"(a[0]), "r"(a[1]), "r"(a[2]), "r"(a[3]), "r"(b[0]), "r"(b[1]));
}
__device__ __forceinline__ void ldsm_x4(unsigned (&a)[4], unsigned addr) {
    asm volatile("ldmatrix.sync.aligned.m8n8.x4.shared.b16 {%0,%1,%2,%3}, [%4];"
                 : "=r"(a[0]), "=r"(a[1]), "=r"(a[2]), "=r"(a[3]) : "r"(addr));
}
__device__ __forceinline__ void ldsm_x2(unsigned (&b)[2], unsigned addr) {
    asm volatile("ldmatrix.sync.aligned.m8n8.x2.shared.b16 {%0,%1}, [%2];"
                 : "=r"(b[0]), "=r"(b[1]) : "r"(addr));
}
__device__ __forceinline__ void cp16(unsigned dst_smem, const void* src) {
    asm volatile("cp.async.cg.shared.global [%0], [%1], 16;"
                 :: "r"(dst_smem), "l"(src) : "memory");
}
__device__ __forceinline__ void cp_commit() {
    asm volatile("cp.async.commit_group;" ::: "memory");
}
template<int N>
__device__ __forceinline__ void cp_wait() {
    asm volatile("cp.async.wait_group %0;" :: "n"(N) : "memory");
}

// ----------------------------------------------------------------------------
// Prologue: convert all weights to fp16 words in chunk-major g_wsplit
// ----------------------------------------------------------------------------
__global__ void split_weights_kernel(const float* __restrict__ Wl,
                                     const float* __restrict__ Wr,
                                     const float* __restrict__ Wf)
{
    const int idx = blockIdx.x * blockDim.x + threadIdx.x;   // < 73728
    const int slice = idx >> 13;          // 0..8  (mat*3 + l)
    const int p     = idx & 8191;         // word within 128x128 slice
    const int mat   = slice / 3;          // 0=Wl 1=Wr 2=Wf
    const int l     = slice - mat * 3;
    const float* W = (mat == 0) ? Wl : (mat == 1) ? Wr : Wf;
    const int row = p >> 6;
    const int w64 = p & 63;               // word in 64-word row
    const int kh  = w64 >> 5;             // k-half
    const int c32 = w64 & 31;
    const float e0 = W[(size_t)(l * 128 + row) * 128 + 2 * w64];
    const float e1 = W[(size_t)(l * 128 + row) * 128 + 2 * w64 + 1];
    const unsigned hw = pack_f16(e0, e1);
    unsigned off;
    if (mat == 2) off = GW_C0 + (l * 2 + kh) * GWC_C + row * 32 + c32;
    else          off = (l * 2 + kh) * GWC_A + mat * 4096 + row * 32 + c32;
    g_wsplit[off] = hw;
}

// ----------------------------------------------------------------------------
// Chunk compute (n=16 per warp, j-interleaved). 2-pass fp16: xh*W + xl*W.
// ----------------------------------------------------------------------------
#define PARTB (PART_W * 4)          // part stride, bytes = 18432
#define JROWB (8 * WSTRIDE * 4)     // 8 n-rows, bytes = 1152

template<int L>
__device__ __forceinline__ void chunkA_mma(unsigned aab, unsigned bb, int khalf,
                                           float (&yL)[M_DIM][2][4], float (&yR)[M_DIM][2][4]) {
    constexpr int base = L * L;
    constexpr int msz  = 2 * L + 1;
    #pragma unroll
    for (int s = 0; s < 4; ++s) {
        unsigned bL[2][2], bR[2][2];
        #pragma unroll
        for (int j = 0; j < 2; ++j) {
            const unsigned bo = bb + j * JROWB + s * 32;
            ldsm_x2(bL[j], bo);
            ldsm_x2(bR[j], bo + PARTB);
        }
        #pragma unroll
        for (int ml = 0; ml < msz; ++ml) {
            unsigned ah[4], al[4];
            const unsigned ao = aab + (base + ml) * (16 * 272) + (khalf * 4 + s) * 32;
            ldsm_x4(ah, ao + OFF_XH * 4);
            ldsm_x4(al, ao + OFF_XL * 4);
            #pragma unroll
            for (int j = 0; j < 2; ++j) { mma16(yL[base + ml][j], ah, bL[j]);
                                          mma16(yR[base + ml][j], ah, bR[j]); }
            #pragma unroll
            for (int j = 0; j < 2; ++j) { mma16(yL[base + ml][j], al, bL[j]);
                                          mma16(yR[base + ml][j], al, bR[j]); }
        }
    }
}

template<int L>
__device__ __forceinline__ void chunkC_mma(unsigned aab, unsigned bb, int khalf,
                                           float (&fo)[M_DIM][2][4]) {
    constexpr int base = L * L;
    constexpr int msz  = 2 * L + 1;
    #pragma unroll
    for (int s = 0; s < 4; ++s) {
        unsigned bF[2][2];
        #pragma unroll
        for (int j = 0; j < 2; ++j)
            ldsm_x2(bF[j], bb + j * JROWB + s * 32);
        #pragma unroll
        for (int ml = 0; ml < msz; ++ml) {
            unsigned ah[4], al[4];
            const unsigned ao = aab + (base + ml) * (16 * 272) + (khalf * 4 + s) * 32;
            ldsm_x4(ah, ao + OFF_XH * 4);
            ldsm_x4(al, ao + OFF_XL * 4);
            #pragma unroll
            for (int j = 0; j < 2; ++j) mma16(fo[base + ml][j], ah, bF[j]);
            #pragma unroll
            for (int j = 0; j < 2; ++j) mma16(fo[base + ml][j], al, bF[j]);
        }
    }
}

// CG tensor product for one (node, channel)
__device__ __forceinline__ void tp_compute(const float (&L)[M_DIM], const float (&R)[M_DIM],
                                           float (&t)[M_DIM], const W3J& P) {
    {   // (2,2,0)
        float v = 0.f;
        #pragma unroll
        for (int i = 0; i < 5; ++i)
            #pragma unroll
            for (int j = 0; j < 5; ++j)
                v = fmaf(P.w220[i * 5 + j], L[4 + i] * R[4 + j], v);
        t[0] = v;
    }
    #pragma unroll
    for (int k = 0; k < 3; ++k) {   // (1,2,1)
        float v = 0.f;
        #pragma unroll
        for (int i = 0; i < 3; ++i)
            #pragma unroll
            for (int j = 0; j < 5; ++j)
                v = fmaf(P.w121[(i * 5 + j) * 3 + k], L[1 + i] * R[4 + j], v);
        t[1 + k] = v;
    }
    #pragma unroll
    for (int k = 0; k < 5; ++k) {   // (1,1,2)
        float v = 0.f;
        #pragma unroll
        for (int i = 0; i < 3; ++i)
            #pragma unroll
            for (int j = 0; j < 3; ++j)
                v = fmaf(P.w112[(i * 3 + j) * 5 + k], L[1 + i] * R[1 + j], v);
        t[4 + k] = v;
    }
}

// ----------------------------------------------------------------------------
// Fused kernel. 256 threads = 8 warps; warp wq owns channels [16wq, 16wq+16).
// Warp-PRIVATE weight pipelines; block barriers only at x-ready/pre-TP/post-TP.
// ----------------------------------------------------------------------------
__global__ __launch_bounds__(THREADS, 1)
void b2i_f16x2_kernel(const float* __restrict__ x,
                      const float* __restrict__ bl,
                      const float* __restrict__ br,
                      const float* __restrict__ bf,
                      float* __restrict__ out, const W3J P)
{
    extern __shared__ unsigned sm[];

    const int tid  = threadIdx.x;
    const int lane = tid & 31;
    const int wq   = tid >> 5;
    const int g    = lane >> 2;
    const int tg   = lane & 3;
    const size_t node0 = (size_t)blockIdx.x * B_NODES;

    const unsigned smb = (unsigned)__cvta_generic_to_shared(sm);
    const unsigned aab = smb + (((lane & 7) + ((lane >> 3) & 1) * 8) * XSTRIDE
                                + (lane >> 4) * 4) * 4;
    const unsigned bwb = ((lane & 7) * WSTRIDE + ((lane >> 3) & 1) * 4) * 4
                       + (16 * wq) * WSTRIDE * 4;

    // warp-private prefetch: copy THIS warp's 16 rows of chunk into slot chunk&1
    auto prefetchW = [&](int chunk) {
        const bool isA = chunk < 6;
        const unsigned* gsrc = g_wsplit + (isA ? chunk * GWC_A
                                              : GW_C0 + (chunk - 6) * GWC_C);
        const int ni = isA ? 8 : 4;          // float4s per lane (2 or 1 parts)
        const unsigned dbase = WBUF0 + (chunk & 1) * WBUF_WORDS;
        for (int i = 0; i < ni; ++i) {
            const int idx  = lane + i * 32;  // float4 index within warp slice
            const int part = idx >> 7;       // 128 float4 per part-slice
            const int r    = 16 * wq + ((idx >> 3) & 15);
            const int c4   = idx & 7;
            cp16(smb + (dbase + part * PART_W + r * WSTRIDE + c4 * 4) * 4,
                 gsrc + part * 4096 + r * 32 + c4 * 4);
        }
        cp_commit();
    };

    prefetchW(0);
    prefetchW(1);

    // ---- stage + split x tile: [node][m][c] -> rows (m*16+node), fp16 hi/lo ----
    {
        #pragma unroll
        for (int i = 0; i < 18; ++i) {
            const int idx = tid + i * THREADS;     // 0..4607 float4s
            const int row = idx >> 5;              // node*9+m
            const int c4  = idx & 31;
            const int node = (row * 57) >> 9;      // row/9 for row<144
            const int m    = row - node * 9;
            const float4 v = __ldg(reinterpret_cast<const float4*>(
                x + ((node0 + node) * M_DIM + m) * C_DIM + c4 * 4));
            unsigned h0, l0, h1, l1;
            split_pair_f16(v.x, v.y, h0, l0);
            split_pair_f16(v.z, v.w, h1, l1);
            const int w = (m * 16 + node) * XSTRIDE + c4 * 2;
            *reinterpret_cast<uint2*>(sm + OFF_XH + w) = make_uint2(h0, h1);
            *reinterpret_cast<uint2*>(sm + OFF_XL + w) = make_uint2(l0, l1);
        }
    }
    __syncthreads();   // x tile ready for all warps

    float yL[M_DIM][2][4], yR[M_DIM][2][4];
    #pragma unroll
    for (int m = 0; m < M_DIM; ++m)
        #pragma unroll
        for (int j = 0; j < 2; ++j)
            #pragma unroll
            for (int c = 0; c < 4; ++c) { yL[m][j][c] = 0.f; yR[m][j][c] = 0.f; }

    #define BB(i) (smb + (WBUF0 + ((i) & 1) * WBUF_WORDS) * 4 + bwb)
    #define CHUNKW(i, WN, BODY)                    \
        do {                                       \
            cp_wait<WN>();                         \
            __syncwarp();                          \
            BODY;                                  \
            if ((i) + 2 <= 11) prefetchW((i) + 2); \
        } while (0)

    // ---- stage A: 6 chunks (l, khalf), Wl+Wr fused; no block barriers ----
    CHUNKW(0, 1, chunkA_mma<0>(aab, BB(0), 0, yL, yR));
    CHUNKW(1, 1, chunkA_mma<0>(aab, BB(1), 1, yL, yR));
    CHUNKW(2, 1, chunkA_mma<1>(aab, BB(2), 0, yL, yR));
    CHUNKW(3, 1, chunkA_mma<1>(aab, BB(3), 1, yL, yR));
    CHUNKW(4, 1, chunkA_mma<2>(aab, BB(4), 0, yL, yR));
    CHUNKW(5, 1, chunkA_mma<2>(aab, BB(5), 1, yL, yR));

    __syncthreads();   // all warps' stage-A reads of x done before t overwrite

    // ---- stage B: thread-local tensor product; t split -> x region ----
    #pragma unroll
    for (int j = 0; j < 2; ++j) {
        const int ch0 = 16 * wq + 8 * j + 2 * tg;
        const int cw  = ch0 >> 1;
        const float bl0 = bl[ch0], bl1 = bl[ch0 + 1];
        const float br0 = br[ch0], br1 = br[ch0 + 1];

        float La[M_DIM], Ra[M_DIM], Lb[M_DIM], Rb[M_DIM], ta[M_DIM], tb[M_DIM];

        // node g
        #pragma unroll
        for (int m = 0; m < M_DIM; ++m) {
            La[m] = yL[m][j][0]; Ra[m] = yR[m][j][0];
            Lb[m] = yL[m][j][1]; Rb[m] = yR[m][j][1];
        }
        La[0] += bl0; Ra[0] += br0; Lb[0] += bl1; Rb[0] += br1;
        tp_compute(La, Ra, ta, P);
        tp_compute(Lb, Rb, tb, P);
        #pragma unroll
        for (int m = 0; m < M_DIM; ++m) {
            unsigned h, lo;
            split_pair_f16(ta[m], tb[m], h, lo);
            const int w = (m * 16 + g) * XSTRIDE + cw;
            sm[OFF_XH + w] = h; sm[OFF_XL + w] = lo;
        }

        // node g+8
        #pragma unroll
        for (int m = 0; m < M_DIM; ++m) {
            La[m] = yL[m][j][2]; Ra[m] = yR[m][j][2];
            Lb[m] = yL[m][j][3]; Rb[m] = yR[m][j][3];
        }
        La[0] += bl0; Ra[0] += br0; Lb[0] += bl1; Rb[0] += br1;
        tp_compute(La, Ra, ta, P);
        tp_compute(Lb, Rb, tb, P);
        #pragma unroll
        for (int m = 0; m < M_DIM; ++m) {
            unsigned h, lo;
            split_pair_f16(ta[m], tb[m], h, lo);
            const int w = (m * 16 + g + 8) * XSTRIDE + cw;
            sm[OFF_XH + w] = h; sm[OFF_XL + w] = lo;
        }
    }
    __syncthreads();   // t tile ready for all warps

    // ---- stage C: 6 chunks (l, khalf); warp-private pipeline continues ----
    float fo[M_DIM][2][4];
    #pragma unroll
    for (int m = 0; m < M_DIM; ++m)
        #pragma unroll
        for (int j = 0; j < 2; ++j)
            #pragma unroll
            for (int c = 0; c < 4; ++c) fo[m][j][c] = 0.f;

    CHUNKW(6,  1, chunkC_mma<0>(aab, BB(6),  0, fo));
    CHUNKW(7,  1, chunkC_mma<0>(aab, BB(7),  1, fo));
    CHUNKW(8,  1, chunkC_mma<1>(aab, BB(8),  0, fo));
    CHUNKW(9,  1, chunkC_mma<1>(aab, BB(9),  1, fo));
    CHUNKW(10, 1, chunkC_mma<2>(aab, BB(10), 0, fo));
    CHUNKW(11, 0, chunkC_mma<2>(aab, BB(11), 1, fo));

    #undef CHUNKW
    #undef BB

    // ---- bias + write out ----
    #pragma unroll
    for (int j = 0; j < 2; ++j) {
        const int ch0 = 16 * wq + 8 * j + 2 * tg;
        const float bf0 = bf[ch0], bf1 = bf[ch0 + 1];
        #pragma unroll
        for (int m = 0; m < M_DIM; ++m) {
            float v0 = fo[m][j][0], v1 = fo[m][j][1], v2 = fo[m][j][2], v3 = fo[m][j][3];
            if (m == 0) { v0 += bf0; v1 += bf1; v2 += bf0; v3 += bf1; }
            const size_t nA = node0 + g;
            const size_t nB = node0 + g + 8;
            *reinterpret_cast<float2*>(out + (nA * M_DIM + m) * C_DIM + ch0) =
                make_float2(v0, v1);
            *reinterpret_cast<float2*>(out + (nB * M_DIM + m) * C_DIM + ch0) =
                make_float2(v2, v3);
        }
    }
}

// ----------------------------------------------------------------------------
// Launch
// ----------------------------------------------------------------------------
extern "C" void kernel_launch(void* const* d_in, const int* in_sizes, int n_in,
                              void* d_out, int out_size)
{
    const float* x  = (const float*)d_in[0];
    const float* Wl = (const float*)d_in[1];
    const float* bl = (const float*)d_in[2];
    const float* Wr = (const float*)d_in[3];
    const float* br = (const float*)d_in[4];
    const float* Wf = (const float*)d_in[5];
    const float* bf = (const float*)d_in[6];
    float* out = (float*)d_out;

    W3J P;
    hw3j::build(P);

    split_weights_kernel<<<288, 256>>>(Wl, Wr, Wf);

    cudaFuncSetAttribute(b2i_f16x2_kernel, cudaFuncAttributeMaxDynamicSharedMemorySize, SMEM_BYTES);
    b2i_f16x2_kernel<<<NNODES / B_NODES, THREADS, SMEM_BYTES>>>(
        x, bl, br, bf, out, P);
}